// round 7
// baseline (speedup 1.0000x reference)
#include <cuda_runtime.h>
#include <cuda_bf16.h>

// ---------------------------------------------------------------------------
// HardTripletMiningLoss  (n=3B=480, D=128)
//   gram = E E^T ;  pd[i,j] = max(sq_i + sq_j - 2 gram_ij, 0)
//   loss = mean over {i!=0, lab[i]==lab[j], lab[k]!=lab[j], td>0} of
//          td = pd[i,j] - pd[j,k] + A
// R7: gram with float4 smem operands: As row-major (f4 over k), Bs TRANSPOSED
//     k-major (f4 over cols). 32x64 tile, 4x4/thread, 128 thr, 120 blocks.
//     Inner loop: 8 LDS.128 + 64 FMA per 4 k's (was 24 LDS + 36 FMA).
// ---------------------------------------------------------------------------

#define MAX_N    768
#define MAXW     ((MAX_N + 31) / 32)
#define POSCAP   128
#define MARGIN_A 0.2f
#define TMR      32     // tile rows
#define TNC      64     // tile cols
#define ASTRIDE  132    // As row stride (mult of 4 -> aligned float4)
#define MAXD     128

static __device__ float g_gram[MAX_N * MAX_N];
static __device__ float g_sq[MAX_N];
static __device__ float g_ps[MAX_N];
static __device__ int   g_pc[MAX_N];

__device__ __forceinline__ const float* row_ptr(const float* a, const float* p,
                                                const float* ng, int r, int B, int D) {
    if (r < B)      return a  + (size_t)r * D;
    if (r < 2 * B)  return p  + (size_t)(r - B) * D;
    return ng + (size_t)(r - 2 * B) * D;
}

// ---------------------------------------------------------------------------
// gram kernel: grid (ceil(n/64), ceil(n/32)), 128 threads, 4x4 per thread.
// ---------------------------------------------------------------------------
__global__ void gram_kernel(const float* __restrict__ anchor,
                            const float* __restrict__ positive,
                            const float* __restrict__ negative,
                            int n, int B, int D) {
    __shared__ float As[TMR][ASTRIDE];   // row-major: As[r][k]
    __shared__ float BsT[MAXD][TNC];     // k-major:  BsT[k][col]

    const int bi  = blockIdx.y * TMR;
    const int bj  = blockIdx.x * TNC;
    const int tid = threadIdx.x;         // 128 threads
    const int nf4 = D >> 2;

    // load As: (r, c4), c4 fastest -> coalesced; aligned float4 smem stores
    for (int idx = tid; idx < TMR * nf4; idx += 128) {
        const int r  = idx / nf4;
        const int c4 = idx - r * nf4;
        const int gr = (bi + r < n) ? bi + r : n - 1;
        const float4 v = ((const float4*)row_ptr(anchor, positive, negative, gr, B, D))[c4];
        *(float4*)&As[r][c4 * 4] = v;
    }
    // load BsT transposed: (c4, col), col fastest -> conflict-free STS
    for (int idx = tid; idx < TNC * nf4; idx += 128) {
        const int c4  = idx / TNC;
        const int col = idx - c4 * TNC;
        const int gc  = (bj + col < n) ? bj + col : n - 1;
        const float4 v = ((const float4*)row_ptr(anchor, positive, negative, gc, B, D))[c4];
        const int k = c4 * 4;
        BsT[k + 0][col] = v.x;
        BsT[k + 1][col] = v.y;
        BsT[k + 2][col] = v.z;
        BsT[k + 3][col] = v.w;
    }
    __syncthreads();

    const int tx = tid & 15;            // 16 col-groups
    const int ty = tid >> 4;            // 8 row-groups
    const int r0 = ty * 4;
    const int c0 = tx * 4;

    float acc[4][4];
    #pragma unroll
    for (int i = 0; i < 4; i++)
        #pragma unroll
        for (int q = 0; q < 4; q++) acc[i][q] = 0.f;

    #pragma unroll 4
    for (int k4 = 0; k4 < nf4; k4++) {
        const int k = k4 * 4;
        float a[4][4];
        #pragma unroll
        for (int i = 0; i < 4; i++) {
            const float4 av = *(const float4*)&As[r0 + i][k];   // broadcast per phase
            a[i][0] = av.x; a[i][1] = av.y; a[i][2] = av.z; a[i][3] = av.w;
        }
        #pragma unroll
        for (int kk = 0; kk < 4; kk++) {
            const float4 b = *(const float4*)&BsT[k + kk][c0];  // 128B contig per phase
            #pragma unroll
            for (int i = 0; i < 4; i++) {
                acc[i][0] = fmaf(a[i][kk], b.x, acc[i][0]);
                acc[i][1] = fmaf(a[i][kk], b.y, acc[i][1]);
                acc[i][2] = fmaf(a[i][kk], b.z, acc[i][2]);
                acc[i][3] = fmaf(a[i][kk], b.w, acc[i][3]);
            }
        }
    }

    const int gj0 = bj + c0;
    #pragma unroll
    for (int i = 0; i < 4; i++) {
        const int gi = bi + r0 + i;
        if (gi < n && gj0 < n) {     // n%4==0, gj0%4==0 -> full float4 in-bounds
            float4 v;
            v.x = acc[i][0]; v.y = acc[i][1]; v.z = acc[i][2]; v.w = acc[i][3];
            *(float4*)&g_gram[(size_t)gi * n + gj0] = v;
            const int dq = gi - gj0;
            if (dq >= 0 && dq < 4) g_sq[gi] = acc[i][dq];
        }
    }
}

// ---------------------------------------------------------------------------
// Triplet: one block (128 thr) per j. Reconstruct pdrow from gram row + sq,
// ballot compaction, branch-free fp32 hot loop, (float,int) partials out.
// ---------------------------------------------------------------------------
__global__ void triplet_kernel(const int* __restrict__ ind, int n) {
    __shared__ float    pdrow[MAX_N];
    __shared__ float    sq_s[MAX_N];
    __shared__ int      labs[MAX_N];
    __shared__ float    avals[POSCAP];
    __shared__ unsigned chunkMask[MAXW];
    __shared__ int      chunkOff[MAXW];
    __shared__ int      nSame;
    __shared__ float    red_s[4];
    __shared__ int      red_c[4];

    const int j    = blockIdx.x;
    const int tid  = threadIdx.x;
    const int lane = tid & 31;
    const int wid  = tid >> 5;

    const float* rowp = g_gram + (size_t)j * n;
    const int n4 = n >> 2;
    for (int v = tid; v < n4; v += 128) {
        ((float4*)pdrow)[v] = ((const float4*)rowp)[v];
        ((float4*)sq_s)[v]  = ((const float4*)g_sq)[v];
    }
    for (int v = (n4 << 2) + tid; v < n; v += 128) {
        pdrow[v] = rowp[v];
        sq_s[v]  = g_sq[v];
    }
    for (int t = tid; t < n; t += 128)
        labs[t] = ind[t];
    __syncthreads();

    // reconstruct pd row: pd = max(sq_j + sq_t - 2*gram, 0)
    const float sqj = sq_s[j];
    for (int t = tid; t < n; t += 128)
        pdrow[t] = fmaxf(fmaf(-2.f, pdrow[t], sqj + sq_s[t]), 0.f);
    __syncthreads();

    const int labj = labs[j];

    // ballot compaction of same-label i's (i != 0), deterministic order
    const int nChunks = (n + 31) >> 5;
    for (int c = wid; c < nChunks; c += 4) {
        const int t = (c << 5) + lane;
        const bool pred = (t < n) && (t != 0) && (labs[t] == labj);
        const unsigned m = __ballot_sync(0xffffffffu, pred);
        if (lane == 0) chunkMask[c] = m;
    }
    __syncthreads();
    if (tid == 0) {
        int off = 0;
        for (int c = 0; c < nChunks; c++) { chunkOff[c] = off; off += __popc(chunkMask[c]); }
        nSame = off;
    }
    __syncthreads();
    for (int c = wid; c < nChunks; c += 4) {
        const unsigned m = chunkMask[c];
        const int t = (c << 5) + lane;
        if ((m >> lane) & 1u)
            avals[chunkOff[c] + __popc(m & ((1u << lane) - 1u))] = pdrow[t] + MARGIN_A;
    }
    __syncthreads();

    // this thread's diff-label pd values in 4 register slots
    float pdk[4];
    #pragma unroll
    for (int m = 0; m < 4; m++) pdk[m] = 3.4e38f;   // sentinel: never counted
    {
        int m = 0;
        for (int k = tid; k < n; k += 128, m++)
            if (labs[k] != labj) pdk[m] = pdrow[k];
    }

    const int ns = nSame;
    float s = 0.f;
    int   c = 0;
    for (int q = 0; q < ns; q++) {
        const float aq = avals[q];
        #pragma unroll
        for (int m = 0; m < 4; m++) {
            const float v = aq - pdk[m];
            if (v > 0.f) { s += v; c++; }
        }
    }

    #pragma unroll
    for (int o = 16; o > 0; o >>= 1) {
        s += __shfl_down_sync(0xffffffffu, s, o);
        c += __shfl_down_sync(0xffffffffu, c, o);
    }
    if (lane == 0) { red_s[wid] = s; red_c[wid] = c; }
    __syncthreads();
    if (tid == 0) {
        float st = 0.f; int ct = 0;
        #pragma unroll
        for (int w = 0; w < 4; w++) { st += red_s[w]; ct += red_c[w]; }
        g_ps[j] = st;
        g_pc[j] = ct;
    }
}

// ---------------------------------------------------------------------------
// Final: single block, fp64 reduce of n partials.
// ---------------------------------------------------------------------------
__global__ void final_kernel(float* __restrict__ out, int n) {
    __shared__ double red_s[4];
    __shared__ double red_c[4];
    const int tid  = threadIdx.x;
    const int lane = tid & 31;
    const int wid  = tid >> 5;

    double s = 0.0, c = 0.0;
    for (int t = tid; t < n; t += 128) { s += (double)g_ps[t]; c += (double)g_pc[t]; }
    #pragma unroll
    for (int o = 16; o > 0; o >>= 1) {
        s += __shfl_down_sync(0xffffffffu, s, o);
        c += __shfl_down_sync(0xffffffffu, c, o);
    }
    if (lane == 0) { red_s[wid] = s; red_c[wid] = c; }
    __syncthreads();
    if (tid == 0) {
        double st = 0.0, ct = 0.0;
        #pragma unroll
        for (int w = 0; w < 4; w++) { st += red_s[w]; ct += red_c[w]; }
        out[0] = (ct > 0.0) ? (float)(st / (ct < 1.0 ? 1.0 : ct)) : 0.0f;
    }
}

extern "C" void kernel_launch(void* const* d_in, const int* in_sizes, int n_in,
                              void* d_out, int out_size) {
    const float* anchor   = (const float*)d_in[0];
    const float* positive = (const float*)d_in[1];
    const float* negative = (const float*)d_in[2];
    const int*   ind      = (const int*)d_in[3];

    const int n = in_sizes[3];          // 3B
    const int B = n / 3;
    const int D = in_sizes[0] / B;

    dim3 grid((n + TNC - 1) / TNC, (n + TMR - 1) / TMR);   // 8 x 15 = 120 blocks
    gram_kernel<<<grid, 128>>>(anchor, positive, negative, n, B, D);
    triplet_kernel<<<n, 128>>>(ind, n);
    final_kernel<<<1, 128>>>((float*)d_out, n);
}

// round 8
// speedup vs baseline: 1.1067x; 1.1067x over previous
#include <cuda_runtime.h>
#include <cuda_bf16.h>

// ---------------------------------------------------------------------------
// HardTripletMiningLoss  (n=3B=480, D=128)
//   gram = E E^T ;  pd[i,j] = max(sq_i + sq_j - 2 gram_ij, 0)
//   loss = mean over {i!=0, lab[i]==lab[j], lab[k]!=lab[j], td>0} of
//          td = pd[i,j] - pd[j,k] + A
// R8: occupancy fix. Gram = R5-proven 32x32/2x2/256thr shape, K SPLIT 4-WAYS
//     (grid 15x15x4 = 900 blocks, ~48 warps/SM vs 12). Partial grams summed
//     in triplet's row reconstruction.
// ---------------------------------------------------------------------------

#define MAX_N    768
#define MAXW     ((MAX_N + 31) / 32)
#define POSCAP   128
#define MARGIN_A 0.2f
#define TILE     32
#define KSPLIT   4
#define KCMAX    32     // D/KSPLIT for D=128
#define DS       (KCMAX + 1)

static __device__ float g_part[KSPLIT][MAX_N * MAX_N];
static __device__ float g_sqp [KSPLIT][MAX_N];
static __device__ float g_ps[MAX_N];
static __device__ int   g_pc[MAX_N];

__device__ __forceinline__ const float* row_ptr(const float* a, const float* p,
                                                const float* ng, int r, int B, int D) {
    if (r < B)      return a  + (size_t)r * D;
    if (r < 2 * B)  return p  + (size_t)(r - B) * D;
    return ng + (size_t)(r - 2 * B) * D;
}

// ---------------------------------------------------------------------------
// gram kernel: grid (n/32, n/32, KSPLIT), 256 thr, 32x32 tile, 2x2/thread.
// Each z-slice accumulates over its K-chunk into g_part[z].
// ---------------------------------------------------------------------------
__global__ void gram_kernel(const float* __restrict__ anchor,
                            const float* __restrict__ positive,
                            const float* __restrict__ negative,
                            int n, int B, int D) {
    __shared__ float As[TILE][DS];
    __shared__ float Bs[TILE][DS];

    const int bi  = blockIdx.y * TILE;
    const int bj  = blockIdx.x * TILE;
    const int z   = blockIdx.z;
    const int Kc  = D / KSPLIT;          // 32 for D=128
    const int k0  = z * Kc;
    const int tid = threadIdx.x;

    // cooperative tile loads (K-chunk only): Kc/4 float4 per row
    const int nf4 = Kc >> 2;             // 8
    for (int idx = tid; idx < TILE * nf4; idx += 256) {
        const int r  = idx / nf4;
        const int c4 = idx - r * nf4;
        const int ra = (bi + r < n) ? bi + r : n - 1;
        const int rb = (bj + r < n) ? bj + r : n - 1;
        const float4 va = *(const float4*)(row_ptr(anchor, positive, negative, ra, B, D) + k0 + c4 * 4);
        As[r][c4 * 4 + 0] = va.x; As[r][c4 * 4 + 1] = va.y;
        As[r][c4 * 4 + 2] = va.z; As[r][c4 * 4 + 3] = va.w;
        const float4 vb = *(const float4*)(row_ptr(anchor, positive, negative, rb, B, D) + k0 + c4 * 4);
        Bs[r][c4 * 4 + 0] = vb.x; Bs[r][c4 * 4 + 1] = vb.y;
        Bs[r][c4 * 4 + 2] = vb.z; Bs[r][c4 * 4 + 3] = vb.w;
    }
    __syncthreads();

    const int tx = tid & 15;
    const int ty = tid >> 4;
    const int r0 = ty * 2, r1 = r0 + 1;
    const int c0 = tx * 2, c1 = c0 + 1;

    float a00 = 0.f, a01 = 0.f, a10 = 0.f, a11 = 0.f;
    #pragma unroll 8
    for (int k = 0; k < Kc; k++) {
        const float x0 = As[r0][k], x1 = As[r1][k];
        const float y0 = Bs[c0][k], y1 = Bs[c1][k];
        a00 = fmaf(x0, y0, a00);
        a01 = fmaf(x0, y1, a01);
        a10 = fmaf(x1, y0, a10);
        a11 = fmaf(x1, y1, a11);
    }

    float* gp = g_part[z];
    const int gi0 = bi + r0, gi1 = bi + r1;
    const int gj0 = bj + c0, gj1 = bj + c1;
    if (gi0 < n && gj0 < n) gp[(size_t)gi0 * n + gj0] = a00;
    if (gi0 < n && gj1 < n) gp[(size_t)gi0 * n + gj1] = a01;
    if (gi1 < n && gj0 < n) gp[(size_t)gi1 * n + gj0] = a10;
    if (gi1 < n && gj1 < n) gp[(size_t)gi1 * n + gj1] = a11;
    if (gi0 == gj0 && gi0 < n) g_sqp[z][gi0] = a00;
    if (gi0 == gj1 && gi0 < n) g_sqp[z][gi0] = a01;
    if (gi1 == gj0 && gi1 < n) g_sqp[z][gi1] = a10;
    if (gi1 == gj1 && gi1 < n) g_sqp[z][gi1] = a11;
}

// ---------------------------------------------------------------------------
// Triplet: one block (128 thr) per j. Sum 4 gram partials + 4 sq partials,
// reconstruct pdrow, ballot compaction, branch-free fp32 hot loop.
// ---------------------------------------------------------------------------
__global__ void triplet_kernel(const int* __restrict__ ind, int n) {
    __shared__ float    pdrow[MAX_N];
    __shared__ float    sq_s[MAX_N];
    __shared__ int      labs[MAX_N];
    __shared__ float    avals[POSCAP];
    __shared__ unsigned chunkMask[MAXW];
    __shared__ int      chunkOff[MAXW];
    __shared__ int      nSame;
    __shared__ float    red_s[4];
    __shared__ int      red_c[4];

    const int j    = blockIdx.x;
    const int tid  = threadIdx.x;
    const int lane = tid & 31;
    const int wid  = tid >> 5;

    // sum gram partials for row j, and sq partials (vectorized)
    const size_t roff = (size_t)j * n;
    const int n4 = n >> 2;
    for (int v = tid; v < n4; v += 128) {
        float4 g = ((const float4*)(g_part[0] + roff))[v];
        float4 q = ((const float4*)g_sqp[0])[v];
        #pragma unroll
        for (int z = 1; z < KSPLIT; z++) {
            const float4 gz = ((const float4*)(g_part[z] + roff))[v];
            const float4 qz = ((const float4*)g_sqp[z])[v];
            g.x += gz.x; g.y += gz.y; g.z += gz.z; g.w += gz.w;
            q.x += qz.x; q.y += qz.y; q.z += qz.z; q.w += qz.w;
        }
        ((float4*)pdrow)[v] = g;
        ((float4*)sq_s)[v]  = q;
    }
    for (int v = (n4 << 2) + tid; v < n; v += 128) {
        float g = 0.f, q = 0.f;
        #pragma unroll
        for (int z = 0; z < KSPLIT; z++) { g += g_part[z][roff + v]; q += g_sqp[z][v]; }
        pdrow[v] = g;
        sq_s[v]  = q;
    }
    for (int t = tid; t < n; t += 128)
        labs[t] = ind[t];
    __syncthreads();

    // reconstruct pd row: pd = max(sq_j + sq_t - 2*gram, 0)
    const float sqj = sq_s[j];
    for (int t = tid; t < n; t += 128)
        pdrow[t] = fmaxf(fmaf(-2.f, pdrow[t], sqj + sq_s[t]), 0.f);
    __syncthreads();

    const int labj = labs[j];

    // ballot compaction of same-label i's (i != 0), deterministic order
    const int nChunks = (n + 31) >> 5;
    for (int c = wid; c < nChunks; c += 4) {
        const int t = (c << 5) + lane;
        const bool pred = (t < n) && (t != 0) && (labs[t] == labj);
        const unsigned m = __ballot_sync(0xffffffffu, pred);
        if (lane == 0) chunkMask[c] = m;
    }
    __syncthreads();
    if (tid == 0) {
        int off = 0;
        for (int c = 0; c < nChunks; c++) { chunkOff[c] = off; off += __popc(chunkMask[c]); }
        nSame = off;
    }
    __syncthreads();
    for (int c = wid; c < nChunks; c += 4) {
        const unsigned m = chunkMask[c];
        const int t = (c << 5) + lane;
        if ((m >> lane) & 1u)
            avals[chunkOff[c] + __popc(m & ((1u << lane) - 1u))] = pdrow[t] + MARGIN_A;
    }
    __syncthreads();

    // this thread's diff-label pd values in 4 register slots
    float pdk[4];
    #pragma unroll
    for (int m = 0; m < 4; m++) pdk[m] = 3.4e38f;   // sentinel: never counted
    {
        int m = 0;
        for (int k = tid; k < n; k += 128, m++)
            if (labs[k] != labj) pdk[m] = pdrow[k];
    }

    const int ns = nSame;
    float s = 0.f;
    int   c = 0;
    for (int q = 0; q < ns; q++) {
        const float aq = avals[q];
        #pragma unroll
        for (int m = 0; m < 4; m++) {
            const float v = aq - pdk[m];
            if (v > 0.f) { s += v; c++; }
        }
    }

    #pragma unroll
    for (int o = 16; o > 0; o >>= 1) {
        s += __shfl_down_sync(0xffffffffu, s, o);
        c += __shfl_down_sync(0xffffffffu, c, o);
    }
    if (lane == 0) { red_s[wid] = s; red_c[wid] = c; }
    __syncthreads();
    if (tid == 0) {
        float st = 0.f; int ct = 0;
        #pragma unroll
        for (int w = 0; w < 4; w++) { st += red_s[w]; ct += red_c[w]; }
        g_ps[j] = st;
        g_pc[j] = ct;
    }
}

// ---------------------------------------------------------------------------
// Final: single block, fp64 reduce of n partials.
// ---------------------------------------------------------------------------
__global__ void final_kernel(float* __restrict__ out, int n) {
    __shared__ double red_s[4];
    __shared__ double red_c[4];
    const int tid  = threadIdx.x;
    const int lane = tid & 31;
    const int wid  = tid >> 5;

    double s = 0.0, c = 0.0;
    for (int t = tid; t < n; t += 128) { s += (double)g_ps[t]; c += (double)g_pc[t]; }
    #pragma unroll
    for (int o = 16; o > 0; o >>= 1) {
        s += __shfl_down_sync(0xffffffffu, s, o);
        c += __shfl_down_sync(0xffffffffu, c, o);
    }
    if (lane == 0) { red_s[wid] = s; red_c[wid] = c; }
    __syncthreads();
    if (tid == 0) {
        double st = 0.0, ct = 0.0;
        #pragma unroll
        for (int w = 0; w < 4; w++) { st += red_s[w]; ct += red_c[w]; }
        out[0] = (ct > 0.0) ? (float)(st / (ct < 1.0 ? 1.0 : ct)) : 0.0f;
    }
}

extern "C" void kernel_launch(void* const* d_in, const int* in_sizes, int n_in,
                              void* d_out, int out_size) {
    const float* anchor   = (const float*)d_in[0];
    const float* positive = (const float*)d_in[1];
    const float* negative = (const float*)d_in[2];
    const int*   ind      = (const int*)d_in[3];

    const int n = in_sizes[3];          // 3B
    const int B = n / 3;
    const int D = in_sizes[0] / B;      // 128 (divisible by KSPLIT*4)

    dim3 grid((n + TILE - 1) / TILE, (n + TILE - 1) / TILE, KSPLIT);  // 15x15x4
    gram_kernel<<<grid, 256>>>(anchor, positive, negative, n, B, D);
    triplet_kernel<<<n, 128>>>(ind, n);
    final_kernel<<<1, 128>>>((float*)d_out, n);
}

// round 9
// speedup vs baseline: 1.1235x; 1.0152x over previous
#include <cuda_runtime.h>
#include <cuda_bf16.h>

// ---------------------------------------------------------------------------
// HardTripletMiningLoss  (n=3B=480, D=128)
//   gram = E E^T ;  pd[i,j] = max(sq_i + sq_j - 2 gram_ij, 0)
//   loss = mean over {i!=0, lab[i]==lab[j], lab[k]!=lab[j], td>0} of
//          td = pd[i,j] - pd[j,k] + A
// R9: gram 16x128 tile / 2x4 per thread / LDS.128 on k-major BsT / KSPLIT=4
//     (480 blocks, 26 warps/SM). Triplet: fused reconstruct (no sq_s array,
//     one less sync) + warp-scan chunk offsets.
// ---------------------------------------------------------------------------

#define MAX_N    768
#define MAXW     ((MAX_N + 31) / 32)
#define POSCAP   128
#define MARGIN_A 0.2f
#define TROW     16
#define TCOL     128
#define KSPLIT   4
#define KCMAX    32      // D / KSPLIT for D=128
#define ASTR     36      // As row stride (mult of 4 -> aligned float4 stores)

static __device__ float g_part[KSPLIT][MAX_N * MAX_N];
static __device__ float g_sqp [KSPLIT][MAX_N];
static __device__ float g_ps[MAX_N];
static __device__ int   g_pc[MAX_N];

__device__ __forceinline__ const float* row_ptr(const float* a, const float* p,
                                                const float* ng, int r, int B, int D) {
    if (r < B)      return a  + (size_t)r * D;
    if (r < 2 * B)  return p  + (size_t)(r - B) * D;
    return ng + (size_t)(r - 2 * B) * D;
}

// ---------------------------------------------------------------------------
// gram: grid (ceil(n/128), ceil(n/16), KSPLIT), 256 thr.
// Per thread: 2 rows x 4 cols. Inner loop per k: 2 broadcast LDS + 1 LDS.128
// + 8 FMA  (2 B smem per FMA, conflict-free).
// ---------------------------------------------------------------------------
__global__ void gram_kernel(const float* __restrict__ anchor,
                            const float* __restrict__ positive,
                            const float* __restrict__ negative,
                            int n, int B, int D) {
    __shared__ float As[TROW][ASTR];     // row-major over k
    __shared__ float BsT[KCMAX][TCOL];   // k-major: BsT[k][col]

    const int bi  = blockIdx.y * TROW;
    const int bj  = blockIdx.x * TCOL;
    const int z   = blockIdx.z;
    const int Kc  = D / KSPLIT;          // 32
    const int k0  = z * Kc;
    const int tid = threadIdx.x;
    const int nf4 = Kc >> 2;             // 8

    // load As tile: 16 rows x 8 float4
    for (int idx = tid; idx < TROW * nf4; idx += 256) {
        const int r  = idx >> 3;
        const int c4 = idx & 7;
        const int gr = (bi + r < n) ? bi + r : n - 1;
        const float4 v = *(const float4*)(row_ptr(anchor, positive, negative, gr, B, D) + k0 + c4 * 4);
        *(float4*)&As[r][c4 * 4] = v;
    }
    // load BsT transposed: 128 cols x 8 float4, scatter to k-major
    for (int idx = tid; idx < TCOL * nf4; idx += 256) {
        const int col = idx & (TCOL - 1);
        const int c4  = idx >> 7;
        const int gc  = (bj + col < n) ? bj + col : n - 1;
        const float4 v = *(const float4*)(row_ptr(anchor, positive, negative, gc, B, D) + k0 + c4 * 4);
        const int k = c4 * 4;
        BsT[k + 0][col] = v.x;
        BsT[k + 1][col] = v.y;
        BsT[k + 2][col] = v.z;
        BsT[k + 3][col] = v.w;
    }
    __syncthreads();

    const int tx = tid & 31;             // 32 col-groups -> warp spans 32 tx
    const int ty = tid >> 5;             // 8 row-groups
    const int r0 = ty * 2;
    const int c0 = tx * 4;

    float acc0x = 0.f, acc0y = 0.f, acc0z = 0.f, acc0w = 0.f;
    float acc1x = 0.f, acc1y = 0.f, acc1z = 0.f, acc1w = 0.f;

    #pragma unroll 8
    for (int k = 0; k < Kc; k++) {
        const float a0 = As[r0][k];          // warp broadcast
        const float a1 = As[r0 + 1][k];      // warp broadcast
        const float4 b = *(const float4*)&BsT[k][c0];   // conflict-free LDS.128
        acc0x = fmaf(a0, b.x, acc0x);
        acc0y = fmaf(a0, b.y, acc0y);
        acc0z = fmaf(a0, b.z, acc0z);
        acc0w = fmaf(a0, b.w, acc0w);
        acc1x = fmaf(a1, b.x, acc1x);
        acc1y = fmaf(a1, b.y, acc1y);
        acc1z = fmaf(a1, b.z, acc1z);
        acc1w = fmaf(a1, b.w, acc1w);
    }

    float* gp = g_part[z];
    const int gj0 = bj + c0;
    const int gi0 = bi + r0;
    if (gj0 < n) {                       // n%4==0 -> whole float4 in-bounds
        if (gi0 < n) {
            float4 v; v.x = acc0x; v.y = acc0y; v.z = acc0z; v.w = acc0w;
            *(float4*)&gp[(size_t)gi0 * n + gj0] = v;
            const int dq = gi0 - gj0;
            if (dq >= 0 && dq < 4) g_sqp[z][gi0] = (&v.x)[dq];
        }
        if (gi0 + 1 < n) {
            float4 v; v.x = acc1x; v.y = acc1y; v.z = acc1z; v.w = acc1w;
            *(float4*)&gp[(size_t)(gi0 + 1) * n + gj0] = v;
            const int dq = gi0 + 1 - gj0;
            if (dq >= 0 && dq < 4) g_sqp[z][gi0 + 1] = (&v.x)[dq];
        }
    }
}

// ---------------------------------------------------------------------------
// Triplet: one block (128 thr) per j. Fused partial-sum + pd reconstruct,
// ballot compaction + warp-scan offsets, branch-free fp32 hot loop.
// ---------------------------------------------------------------------------
__global__ void triplet_kernel(const int* __restrict__ ind, int n) {
    __shared__ float    pdrow[MAX_N];
    __shared__ int      labs[MAX_N];
    __shared__ float    avals[POSCAP];
    __shared__ unsigned chunkMask[MAXW];
    __shared__ int      chunkOff[MAXW];
    __shared__ int      nSame;
    __shared__ float    red_s[4];
    __shared__ int      red_c[4];

    const int j    = blockIdx.x;
    const int tid  = threadIdx.x;
    const int lane = tid & 31;
    const int wid  = tid >> 5;

    // sqj read directly by every thread (broadcast LDG of 4 partials)
    float sqj = g_sqp[0][j];
    #pragma unroll
    for (int z = 1; z < KSPLIT; z++) sqj += g_sqp[z][j];

    // fused: sum gram/sq partials and reconstruct pd row in ONE pass
    const size_t roff = (size_t)j * n;
    const int n4 = n >> 2;
    for (int v = tid; v < n4; v += 128) {
        float4 g = ((const float4*)(g_part[0] + roff))[v];
        float4 q = ((const float4*)g_sqp[0])[v];
        #pragma unroll
        for (int z = 1; z < KSPLIT; z++) {
            const float4 gz = ((const float4*)(g_part[z] + roff))[v];
            const float4 qz = ((const float4*)g_sqp[z])[v];
            g.x += gz.x; g.y += gz.y; g.z += gz.z; g.w += gz.w;
            q.x += qz.x; q.y += qz.y; q.z += qz.z; q.w += qz.w;
        }
        float4 pd;
        pd.x = fmaxf(fmaf(-2.f, g.x, sqj + q.x), 0.f);
        pd.y = fmaxf(fmaf(-2.f, g.y, sqj + q.y), 0.f);
        pd.z = fmaxf(fmaf(-2.f, g.z, sqj + q.z), 0.f);
        pd.w = fmaxf(fmaf(-2.f, g.w, sqj + q.w), 0.f);
        ((float4*)pdrow)[v] = pd;
    }
    for (int v = (n4 << 2) + tid; v < n; v += 128) {
        float g = 0.f, q = 0.f;
        #pragma unroll
        for (int z = 0; z < KSPLIT; z++) { g += g_part[z][roff + v]; q += g_sqp[z][v]; }
        pdrow[v] = fmaxf(fmaf(-2.f, g, sqj + q), 0.f);
    }
    for (int t = tid; t < n; t += 128)
        labs[t] = ind[t];
    __syncthreads();

    const int labj = labs[j];

    // ballot compaction of same-label i's (i != 0)
    const int nChunks = (n + 31) >> 5;
    for (int c = wid; c < nChunks; c += 4) {
        const int t = (c << 5) + lane;
        const bool pred = (t < n) && (t != 0) && (labs[t] == labj);
        const unsigned m = __ballot_sync(0xffffffffu, pred);
        if (lane == 0) chunkMask[c] = m;
    }
    __syncthreads();
    // warp 0: parallel exclusive scan of chunk popcounts (nChunks <= 32)
    if (wid == 0) {
        const unsigned m = (lane < nChunks) ? chunkMask[lane] : 0u;
        int p = __popc(m);
        #pragma unroll
        for (int o = 1; o < 32; o <<= 1) {
            const int t = __shfl_up_sync(0xffffffffu, p, o);
            if (lane >= o) p += t;
        }
        if (lane < nChunks) chunkOff[lane] = p - __popc(m);
        if (lane == 31) nSame = p;
    }
    __syncthreads();
    for (int c = wid; c < nChunks; c += 4) {
        const unsigned m = chunkMask[c];
        const int t = (c << 5) + lane;
        if ((m >> lane) & 1u) {
            const int off = chunkOff[c] + __popc(m & ((1u << lane) - 1u));
            if (off < POSCAP) avals[off] = pdrow[t] + MARGIN_A;
        }
    }
    __syncthreads();

    // this thread's diff-label pd values in 4 register slots
    float pdk[4];
    #pragma unroll
    for (int m = 0; m < 4; m++) pdk[m] = 3.4e38f;   // sentinel: never counted
    {
        int m = 0;
        for (int k = tid; k < n; k += 128, m++)
            if (labs[k] != labj) pdk[m] = pdrow[k];
    }

    const int ns = (nSame < POSCAP) ? nSame : POSCAP;
    float s = 0.f;
    int   c = 0;
    for (int q = 0; q < ns; q++) {
        const float aq = avals[q];
        #pragma unroll
        for (int m = 0; m < 4; m++) {
            const float v = aq - pdk[m];
            if (v > 0.f) { s += v; c++; }
        }
    }

    #pragma unroll
    for (int o = 16; o > 0; o >>= 1) {
        s += __shfl_down_sync(0xffffffffu, s, o);
        c += __shfl_down_sync(0xffffffffu, c, o);
    }
    if (lane == 0) { red_s[wid] = s; red_c[wid] = c; }
    __syncthreads();
    if (tid == 0) {
        float st = 0.f; int ct = 0;
        #pragma unroll
        for (int w = 0; w < 4; w++) { st += red_s[w]; ct += red_c[w]; }
        g_ps[j] = st;
        g_pc[j] = ct;
    }
}

// ---------------------------------------------------------------------------
// Final: single block, fp64 reduce of n partials.
// ---------------------------------------------------------------------------
__global__ void final_kernel(float* __restrict__ out, int n) {
    __shared__ double red_s[4];
    __shared__ double red_c[4];
    const int tid  = threadIdx.x;
    const int lane = tid & 31;
    const int wid  = tid >> 5;

    double s = 0.0, c = 0.0;
    for (int t = tid; t < n; t += 128) { s += (double)g_ps[t]; c += (double)g_pc[t]; }
    #pragma unroll
    for (int o = 16; o > 0; o >>= 1) {
        s += __shfl_down_sync(0xffffffffu, s, o);
        c += __shfl_down_sync(0xffffffffu, c, o);
    }
    if (lane == 0) { red_s[wid] = s; red_c[wid] = c; }
    __syncthreads();
    if (tid == 0) {
        double st = 0.0, ct = 0.0;
        #pragma unroll
        for (int w = 0; w < 4; w++) { st += red_s[w]; ct += red_c[w]; }
        out[0] = (ct > 0.0) ? (float)(st / (ct < 1.0 ? 1.0 : ct)) : 0.0f;
    }
}

extern "C" void kernel_launch(void* const* d_in, const int* in_sizes, int n_in,
                              void* d_out, int out_size) {
    const float* anchor   = (const float*)d_in[0];
    const float* positive = (const float*)d_in[1];
    const float* negative = (const float*)d_in[2];
    const int*   ind      = (const int*)d_in[3];

    const int n = in_sizes[3];          // 3B
    const int B = n / 3;
    const int D = in_sizes[0] / B;      // 128

    dim3 grid((n + TCOL - 1) / TCOL, (n + TROW - 1) / TROW, KSPLIT);  // 4x30x4
    gram_kernel<<<grid, 256>>>(anchor, positive, negative, n, B, D);
    triplet_kernel<<<n, 128>>>(ind, n);
    final_kernel<<<1, 128>>>((float*)d_out, n);
}